// round 3
// baseline (speedup 1.0000x reference)
#include <cuda_runtime.h>

#define BB 4096
#define II 256
#define OO 256
#define EE 8

// Scratch (no allocations allowed)
__device__ int g_counts[EE];
__device__ int g_rows[EE * BB];

#define FMA2(d, a, b, c) \
    asm("fma.rn.f32x2 %0, %1, %2, %3;" : "=l"(d) : "l"(a), "l"(b), "l"(c))
#define PACK2(d, f) \
    asm("mov.b64 %0, {%1, %1};" : "=l"(d) : "f"(f))
#define UNPACK2(lo, hi, v) \
    asm("mov.b64 {%0, %1}, %2;" : "=f"(lo), "=f"(hi) : "l"(v))

__global__ void init_kernel() {
    if (threadIdx.x < EE) g_counts[threadIdx.x] = 0;
}

// One warp per row: 8 logits, sigmoid, argmax (multi-hot on exact ties).
__global__ void router_kernel(const float* __restrict__ x,
                              const float* __restrict__ Wp,
                              const float* __restrict__ bp,
                              float* __restrict__ y) {
    int warp = threadIdx.x >> 5;
    int lane = threadIdx.x & 31;
    int row = blockIdx.x * 8 + warp;
    if (row >= BB) return;

    const float* xr = x + row * II;
    float xv[8];
#pragma unroll
    for (int c = 0; c < 8; c++) xv[c] = xr[lane + 32 * c];

    float g[EE];
    float gmax = -1e30f;
#pragma unroll
    for (int e = 0; e < EE; e++) {
        const float* wp = Wp + e * II;
        float p = 0.f;
#pragma unroll
        for (int c = 0; c < 8; c++) p += xv[c] * wp[lane + 32 * c];
#pragma unroll
        for (int s = 16; s > 0; s >>= 1) p += __shfl_xor_sync(0xffffffffu, p, s);
        float z = p + bp[e];
        g[e] = 1.0f / (1.0f + expf(-z));   // accurate expf: tie semantics track ref
        gmax = fmaxf(gmax, g[e]);
    }

    unsigned mask = 0;
#pragma unroll
    for (int e = 0; e < EE; e++)
        if (g[e] == gmax) mask |= 1u << e;
    int nsel = __popc(mask);

    if (lane == 0) {
#pragma unroll
        for (int e = 0; e < EE; e++) {
            if (mask & (1u << e)) {
                int pos = atomicAdd(&g_counts[e], 1);
                g_rows[e * BB + pos] = row | (nsel > 1 ? 0x40000000 : 0);
            }
        }
    }
    // Tied rows are summed over experts in pass 2 via atomicAdd -> zero them now.
    if (nsel > 1) {
#pragma unroll
        for (int c = 0; c < 8; c++) y[row * OO + lane + 32 * c] = 0.f;
    }
}

// Per-expert gathered GEMM: TM=32 rows x TN=256 cols, KC=32, 256 threads.
// Each thread: 4 rows x 8 cols, accumulated as 16 packed f32x2 pairs.
__global__ __launch_bounds__(256) void gemm_kernel(const float* __restrict__ x,
                                                   const float* __restrict__ W,
                                                   float* __restrict__ y) {
    __shared__ float As[32][32];    // [k][row]
    __shared__ float Bs[32][256];   // [k][col]
    __shared__ int rowids[32];

    int e = blockIdx.y;
    int tile = blockIdx.x;
    int count = g_counts[e];
    if (tile * 32 >= count) return;
    int nrows = min(32, count - tile * 32);

    int tid = threadIdx.x;
    if (tid < 32) {
        rowids[tid] = (tid < nrows) ? g_rows[e * BB + tile * 32 + tid] : -1;
    }
    __syncthreads();

    int rgrp = tid >> 5;   // 0..7  -> rows rgrp*4 .. +3
    int cgrp = tid & 31;   // 0..31 -> cols cgrp*8 .. +7

    unsigned long long acc[4][4];
#pragma unroll
    for (int r = 0; r < 4; r++)
#pragma unroll
        for (int c = 0; c < 4; c++) acc[r][c] = 0ull;

    // loader roles
    int a_r = tid >> 3;        // 0..31 row
    int a_kq = tid & 7;        // 0..7  -> k = a_kq*4..+3
    int b_kb = tid >> 6;       // 0..3
    int b_c4 = tid & 63;       // float4 col index

    int a_rv = rowids[a_r];
    int a_rid = a_rv & 0x3FFFFFFF;
    const float* wbase = W + (size_t)e * II * OO;

    for (int kc = 0; kc < II; kc += 32) {
        // A tile: gathered rows, float4 along k
        float4 av4 = make_float4(0.f, 0.f, 0.f, 0.f);
        if (a_rv >= 0)
            av4 = *reinterpret_cast<const float4*>(&x[(size_t)a_rid * II + kc + a_kq * 4]);
        As[a_kq * 4 + 0][a_r] = av4.x;
        As[a_kq * 4 + 1][a_r] = av4.y;
        As[a_kq * 4 + 2][a_r] = av4.z;
        As[a_kq * 4 + 3][a_r] = av4.w;

        // B tile: W[e][kc+k][:] rows, coalesced float4
#pragma unroll
        for (int p = 0; p < 8; p++) {
            int k = b_kb * 8 + p;
            float4 bv = *reinterpret_cast<const float4*>(&wbase[(size_t)(kc + k) * OO + b_c4 * 4]);
            *reinterpret_cast<float4*>(&Bs[k][b_c4 * 4]) = bv;
        }
        __syncthreads();

#pragma unroll 8
        for (int k = 0; k < 32; k++) {
            float4 av = *reinterpret_cast<const float4*>(&As[k][rgrp * 4]);
            unsigned long long a2[4];
            PACK2(a2[0], av.x);
            PACK2(a2[1], av.y);
            PACK2(a2[2], av.z);
            PACK2(a2[3], av.w);
            const ulonglong2* bp2 = reinterpret_cast<const ulonglong2*>(&Bs[k][cgrp * 8]);
            ulonglong2 b01 = bp2[0];
            ulonglong2 b23 = bp2[1];
            unsigned long long bb[4] = {b01.x, b01.y, b23.x, b23.y};
#pragma unroll
            for (int r = 0; r < 4; r++)
#pragma unroll
                for (int c = 0; c < 4; c++)
                    FMA2(acc[r][c], a2[r], bb[c], acc[r][c]);
        }
        __syncthreads();
    }

    // store
#pragma unroll
    for (int r = 0; r < 4; r++) {
        int rv = rowids[rgrp * 4 + r];
        if (rv < 0) continue;
        int rid = rv & 0x3FFFFFFF;
        bool multi = (rv & 0x40000000) != 0;
        float* yr = y + (size_t)rid * OO + cgrp * 8;
        float out[8];
#pragma unroll
        for (int c = 0; c < 4; c++) UNPACK2(out[2 * c], out[2 * c + 1], acc[r][c]);
        if (multi) {
#pragma unroll
            for (int j = 0; j < 8; j++) atomicAdd(&yr[j], out[j]);
        } else {
            *reinterpret_cast<float4*>(&yr[0]) = make_float4(out[0], out[1], out[2], out[3]);
            *reinterpret_cast<float4*>(&yr[4]) = make_float4(out[4], out[5], out[6], out[7]);
        }
    }
}

extern "C" void kernel_launch(void* const* d_in, const int* in_sizes, int n_in,
                              void* d_out, int out_size) {
    const float* x  = (const float*)d_in[0];
    const float* W  = (const float*)d_in[1];
    const float* Wp = (const float*)d_in[2];
    const float* bp = (const float*)d_in[3];
    float* y = (float*)d_out;

    init_kernel<<<1, 32>>>();
    router_kernel<<<BB / 8, 256>>>(x, Wp, bp, y);
    dim3 grid(BB / 32, EE);
    gemm_kernel<<<grid, 256>>>(x, W, y);
}

// round 4
// speedup vs baseline: 1.2555x; 1.2555x over previous
#include <cuda_runtime.h>

#define BB 4096
#define II 256
#define OO 256
#define EE 8

// Scratch (no allocations allowed). Zero-initialized at module load;
// gemm's last block re-zeroes g_counts/g_done for the next replay.
__device__ int g_counts[EE * 32];   // counter for expert e lives at [e*32] -> 128B apart (distinct LTS sectors)
__device__ int g_rows[EE * BB];
__device__ int g_done;

#define FMA2(d, a, b, c) \
    asm("fma.rn.f32x2 %0, %1, %2, %3;" : "=l"(d) : "l"(a), "l"(b), "l"(c))
#define PACK2(d, f) \
    asm("mov.b64 %0, {%1, %1};" : "=l"(d) : "f"(f))
#define UNPACK2(lo, hi, v) \
    asm("mov.b64 {%0, %1}, %2;" : "=f"(lo), "=f"(hi) : "l"(v))

// ---------------------------------------------------------------------------
// Router: 64 blocks x 256 threads. Each warp handles 8 rows.
// Per-block smem lists + ONE global atomic per expert per block (512 total,
// on 128B-padded counters) instead of 4096 atomics on one packed sector.
// ---------------------------------------------------------------------------
__global__ __launch_bounds__(256) void router_kernel(const float* __restrict__ x,
                                                     const float* __restrict__ Wp,
                                                     const float* __restrict__ bp,
                                                     float* __restrict__ y) {
    __shared__ float s_wp[EE * II];      // 8KB
    __shared__ float s_bp[EE];
    __shared__ int s_cnt[EE];
    __shared__ int s_base[EE];
    __shared__ int s_list[EE][64];

    int tid = threadIdx.x;
    // Stage Wp into smem (same layout as gmem)
    {
        const float4* Wp4 = reinterpret_cast<const float4*>(Wp);
        float4* swp4 = reinterpret_cast<float4*>(s_wp);
#pragma unroll
        for (int i = 0; i < 2; i++) swp4[tid + 256 * i] = Wp4[tid + 256 * i];
    }
    if (tid < EE) { s_bp[tid] = bp[tid]; s_cnt[tid] = 0; }
    __syncthreads();

    int warp = tid >> 5;
    int lane = tid & 31;
    int e_lane = lane >> 2;              // lanes 4e..4e+3 own expert e after reduce
    const float4* X4 = reinterpret_cast<const float4*>(x);
    float4* Y4 = reinterpret_cast<float4*>(y);

#pragma unroll 1
    for (int i = 0; i < 8; i++) {
        int row = blockIdx.x * 64 + warp * 8 + i;
        float4 xa = X4[row * 64 + lane];
        float4 xb = X4[row * 64 + 32 + lane];

        float p[EE];
#pragma unroll
        for (int e = 0; e < EE; e++) {
            const float4* we = reinterpret_cast<const float4*>(s_wp + e * II);
            float4 wa = we[lane];
            float4 wb = we[32 + lane];
            p[e] = xa.x * wa.x + xa.y * wa.y + xa.z * wa.z + xa.w * wa.w
                 + xb.x * wb.x + xb.y * wb.y + xb.z * wb.z + xb.w * wb.w;
        }
        // Fold lane bits 4,3,2: each lane holds sum over lanes == lane (mod 4)
#pragma unroll
        for (int s = 16; s >= 4; s >>= 1)
#pragma unroll
            for (int e = 0; e < EE; e++)
                p[e] += __shfl_xor_sync(0xffffffffu, p[e], s);
        // Lane 4e+c selects its class-c partial of expert e, fold bits 0,1
        float v = p[0];
#pragma unroll
        for (int j = 1; j < EE; j++) v = (e_lane == j) ? p[j] : v;
        v += __shfl_xor_sync(0xffffffffu, v, 1);
        v += __shfl_xor_sync(0xffffffffu, v, 2);

        float z = v + s_bp[e_lane];
        float g = 1.0f / (1.0f + expf(-z));   // accurate expf: tie semantics track ref

        float m = g;
        m = fmaxf(m, __shfl_xor_sync(0xffffffffu, m, 4));
        m = fmaxf(m, __shfl_xor_sync(0xffffffffu, m, 8));
        m = fmaxf(m, __shfl_xor_sync(0xffffffffu, m, 16));

        unsigned bal = __ballot_sync(0xffffffffu, g == m);
        int nsel = __popc(bal & 0x11111111u);   // experts achieving the max

        if ((g == m) && ((lane & 3) == 0)) {
            int pos = atomicAdd(&s_cnt[e_lane], 1);   // smem atomic, cheap
            s_list[e_lane][pos] = row | (nsel > 1 ? 0x40000000 : 0);
        }
        // Tied rows summed via atomicAdd in gemm -> zero them now.
        if (nsel > 1) {
            Y4[row * 64 + lane] = make_float4(0.f, 0.f, 0.f, 0.f);
            Y4[row * 64 + 32 + lane] = make_float4(0.f, 0.f, 0.f, 0.f);
        }
    }
    __syncthreads();

    if (tid < EE) s_base[tid] = atomicAdd(&g_counts[tid * 32], s_cnt[tid]);
    __syncthreads();

    if (warp < EE) {
        int n = s_cnt[warp];
        int b = s_base[warp];
        for (int j = lane; j < n; j += 32)
            g_rows[warp * BB + b + j] = s_list[warp][j];
    }
}

// ---------------------------------------------------------------------------
// Per-expert gathered GEMM: TM=32 rows x TN=256 cols, KC=32, 256 threads.
// Register-prefetched global loads, A-tile pre-duplicated as f32x2 pairs.
// grid = (EE, 128): expert varies fastest -> live blocks in the first wave.
// Last-finished block resets g_counts/g_done for the next replay.
// ---------------------------------------------------------------------------
__global__ __launch_bounds__(256) void gemm_kernel(const float* __restrict__ x,
                                                   const float* __restrict__ W,
                                                   float* __restrict__ y) {
    __shared__ unsigned long long As2[32][32];   // [k][row] as {v,v} pairs, 8KB
    __shared__ float Bs[32][256];                // [k][col], 32KB
    __shared__ int rowids[32];

    int e = blockIdx.x;
    int tile = blockIdx.y;
    int count = g_counts[e * 32];

    if (tile * 32 < count) {
        int nrows = min(32, count - tile * 32);
        int tid = threadIdx.x;
        if (tid < 32)
            rowids[tid] = (tid < nrows) ? g_rows[e * BB + tile * 32 + tid] : -1;
        __syncthreads();

        int rgrp = tid >> 5;   // 0..7  -> rows rgrp*4 .. +3 (uniform per warp)
        int cgrp = tid & 31;   // 0..31 -> cols cgrp*8 .. +7
        int a_r  = tid >> 3;   // 0..31 A-load row
        int a_kq = tid & 7;    // k = a_kq*4..+3
        int b_kb = tid >> 6;   // 0..3
        int b_c4 = tid & 63;   // float4 col index

        int a_rv = rowids[a_r];
        int a_rid = a_rv & 0x3FFFFFFF;
        const float* wbase = W + (size_t)e * II * OO;
        const float4* xrow4 = reinterpret_cast<const float4*>(x + (size_t)a_rid * II);

        unsigned long long acc[16];
#pragma unroll
        for (int i = 0; i < 16; i++) acc[i] = 0ull;

        // Prefetch chunk 0 into registers
        float4 apre = make_float4(0.f, 0.f, 0.f, 0.f);
        if (a_rv >= 0) apre = xrow4[a_kq];
        float4 bpre[8];
#pragma unroll
        for (int p = 0; p < 8; p++)
            bpre[p] = *reinterpret_cast<const float4*>(&wbase[(size_t)(b_kb * 8 + p) * OO + b_c4 * 4]);

        for (int kc = 0; kc < II; kc += 32) {
            // Commit prefetched chunk to smem
            unsigned long long d0, d1, d2, d3;
            PACK2(d0, apre.x); PACK2(d1, apre.y); PACK2(d2, apre.z); PACK2(d3, apre.w);
            As2[a_kq * 4 + 0][a_r] = d0;
            As2[a_kq * 4 + 1][a_r] = d1;
            As2[a_kq * 4 + 2][a_r] = d2;
            As2[a_kq * 4 + 3][a_r] = d3;
#pragma unroll
            for (int p = 0; p < 8; p++)
                *reinterpret_cast<float4*>(&Bs[b_kb * 8 + p][b_c4 * 4]) = bpre[p];
            __syncthreads();

            // Issue next chunk's global loads (latency hidden under compute)
            if (kc + 32 < II) {
                if (a_rv >= 0) apre = xrow4[(kc + 32) / 4 + a_kq];
#pragma unroll
                for (int p = 0; p < 8; p++)
                    bpre[p] = *reinterpret_cast<const float4*>(
                        &wbase[(size_t)(kc + 32 + b_kb * 8 + p) * OO + b_c4 * 4]);
            }

#pragma unroll 8
            for (int k = 0; k < 32; k++) {
                const ulonglong2* ap = reinterpret_cast<const ulonglong2*>(&As2[k][rgrp * 4]);
                ulonglong2 a01 = ap[0];        // broadcast (uniform addr per warp)
                ulonglong2 a23 = ap[1];
                const ulonglong2* bpp = reinterpret_cast<const ulonglong2*>(&Bs[k][cgrp * 8]);
                ulonglong2 b01 = bpp[0];
                ulonglong2 b23 = bpp[1];
                unsigned long long aa[4] = {a01.x, a01.y, a23.x, a23.y};
                unsigned long long bb[4] = {b01.x, b01.y, b23.x, b23.y};
#pragma unroll
                for (int r = 0; r < 4; r++)
#pragma unroll
                    for (int c = 0; c < 4; c++)
                        FMA2(acc[r * 4 + c], aa[r], bb[c], acc[r * 4 + c]);
            }
            __syncthreads();
        }

        // Epilogue
#pragma unroll
        for (int r = 0; r < 4; r++) {
            int rv = rowids[rgrp * 4 + r];
            if (rv < 0) continue;
            int rid = rv & 0x3FFFFFFF;
            bool multi = (rv & 0x40000000) != 0;
            float* yr = y + (size_t)rid * OO + cgrp * 8;
            float out[8];
#pragma unroll
            for (int c = 0; c < 4; c++) UNPACK2(out[2 * c], out[2 * c + 1], acc[r * 4 + c]);
            if (multi) {
#pragma unroll
                for (int j = 0; j < 8; j++) atomicAdd(&yr[j], out[j]);
            } else {
                *reinterpret_cast<float4*>(&yr[0]) = make_float4(out[0], out[1], out[2], out[3]);
                *reinterpret_cast<float4*>(&yr[4]) = make_float4(out[4], out[5], out[6], out[7]);
            }
        }
    }

    // Last block (work or dead) resets counters for the next replay.
    if (threadIdx.x == 0) {
        int old = atomicAdd(&g_done, 1);
        if (old == EE * 128 - 1) {
#pragma unroll
            for (int i = 0; i < EE; i++) g_counts[i * 32] = 0;
            __threadfence();
            g_done = 0;
        }
    }
}

extern "C" void kernel_launch(void* const* d_in, const int* in_sizes, int n_in,
                              void* d_out, int out_size) {
    const float* x  = (const float*)d_in[0];
    const float* W  = (const float*)d_in[1];
    const float* Wp = (const float*)d_in[2];
    const float* bp = (const float*)d_in[3];
    float* y = (float*)d_out;

    router_kernel<<<64, 256>>>(x, Wp, bp, y);
    dim3 grid(EE, 128);   // expert fastest -> live tiles land in wave 1
    gemm_kernel<<<grid, 256>>>(x, W, y);
}

// round 6
// speedup vs baseline: 3.3170x; 2.6420x over previous
#include <cuda_runtime.h>
#include <cuda_bf16.h>
#include <cstdint>

#define BB 4096
#define II 256
#define OO 256
#define EE 8

// ---------------------------------------------------------------------------
// Device scratch (no allocations allowed). Zero at module load; gemm's last
// block resets g_counts/g_done each replay.
// ---------------------------------------------------------------------------
__device__ int g_counts[EE * 32];     // expert e counter at [e*32] (128B apart)
__device__ int g_rows[EE * BB];
__device__ int g_done;
__device__ __nv_bfloat16 g_xhi[BB * II];
__device__ __nv_bfloat16 g_xlo[BB * II];
__device__ __nv_bfloat16 g_whi[EE * OO * II];   // transposed: [e][o][i]
__device__ __nv_bfloat16 g_wlo[EE * OO * II];

__device__ __forceinline__ uint32_t smem_to_u32(const void* p) {
    uint32_t a;
    asm("{ .reg .u64 t; cvta.to.shared.u64 t, %1; cvt.u32.u64 %0, t; }" : "=r"(a) : "l"(p));
    return a;
}
__device__ __forceinline__ void cp16(uint32_t dst, const void* src) {
    asm volatile("cp.async.cg.shared.global [%0], [%1], 16;" :: "r"(dst), "l"(src));
}
// D += A*B, m16n8k16 bf16 -> f32
#define MMA(d, a, b) \
    asm volatile( \
        "mma.sync.aligned.m16n8k16.row.col.f32.bf16.bf16.f32 " \
        "{%0,%1,%2,%3}, {%4,%5,%6,%7}, {%8,%9}, {%0,%1,%2,%3};" \
        : "+f"((d)[0]), "+f"((d)[1]), "+f"((d)[2]), "+f"((d)[3]) \
        : "r"((a)[0]), "r"((a)[1]), "r"((a)[2]), "r"((a)[3]), \
          "r"((b)[0]), "r"((b)[1]))

__device__ __forceinline__ unsigned pk(__nv_bfloat16 a, __nv_bfloat16 b) {
    __nv_bfloat162 t(a, b);
    return *reinterpret_cast<unsigned*>(&t);
}
__device__ __forceinline__ void split4(float4 v, uint2& h, uint2& l) {
    __nv_bfloat16 h0 = __float2bfloat16(v.x), h1 = __float2bfloat16(v.y);
    __nv_bfloat16 h2 = __float2bfloat16(v.z), h3 = __float2bfloat16(v.w);
    __nv_bfloat16 l0 = __float2bfloat16(v.x - __bfloat162float(h0));
    __nv_bfloat16 l1 = __float2bfloat16(v.y - __bfloat162float(h1));
    __nv_bfloat16 l2 = __float2bfloat16(v.z - __bfloat162float(h2));
    __nv_bfloat16 l3 = __float2bfloat16(v.w - __bfloat162float(h3));
    h.x = pk(h0, h1); h.y = pk(h2, h3);
    l.x = pk(l0, l1); l.y = pk(l2, l3);
}

// ---------------------------------------------------------------------------
// Prep kernel: blocks 0..63 router (+ x bf16 split), blocks 64..127 W split+transpose.
// ---------------------------------------------------------------------------
__global__ __launch_bounds__(256) void prep_kernel(const float* __restrict__ x,
                                                   const float* __restrict__ W,
                                                   const float* __restrict__ Wp,
                                                   const float* __restrict__ bp,
                                                   float* __restrict__ y) {
    __shared__ float s_wp[EE * II];
    __shared__ float s_bp[EE];
    __shared__ int s_cnt[EE];
    __shared__ int s_base[EE];
    __shared__ int s_list[EE][64];
    __shared__ float s_t[256][33];

    int tid = threadIdx.x;

    if (blockIdx.x >= 64) {
        // ---- W conversion: W[e][i][o] fp32 -> g_whi/g_wlo [e][o][i] bf16 ----
        int b = blockIdx.x - 64;            // 0..63
        int e = b >> 3;
        int o0 = (b & 7) * 32;
        const float* wb = W + (size_t)e * II * OO;
#pragma unroll
        for (int j = 0; j < 8; j++) {
            float4 v = *reinterpret_cast<const float4*>(&wb[(size_t)tid * OO + o0 + j * 4]);
            s_t[tid][j * 4 + 0] = v.x; s_t[tid][j * 4 + 1] = v.y;
            s_t[tid][j * 4 + 2] = v.z; s_t[tid][j * 4 + 3] = v.w;
        }
        __syncthreads();
        int ol = tid >> 3;                  // 0..31 -> output row o0+ol
        int i0 = (tid & 7) * 32;            // 32 consecutive i per thread
        unsigned hp[16], lp[16];
#pragma unroll
        for (int j = 0; j < 16; j++) {
            float a = s_t[i0 + 2 * j][ol];
            float c = s_t[i0 + 2 * j + 1][ol];
            __nv_bfloat16 ha = __float2bfloat16(a), hc = __float2bfloat16(c);
            __nv_bfloat16 la = __float2bfloat16(a - __bfloat162float(ha));
            __nv_bfloat16 lc = __float2bfloat16(c - __bfloat162float(hc));
            hp[j] = pk(ha, hc);
            lp[j] = pk(la, lc);
        }
        size_t base = ((size_t)e * OO + o0 + ol) * II + i0;
        uint4* dh = reinterpret_cast<uint4*>(g_whi + base);
        uint4* dl = reinterpret_cast<uint4*>(g_wlo + base);
#pragma unroll
        for (int q = 0; q < 4; q++) {
            dh[q] = make_uint4(hp[q * 4], hp[q * 4 + 1], hp[q * 4 + 2], hp[q * 4 + 3]);
            dl[q] = make_uint4(lp[q * 4], lp[q * 4 + 1], lp[q * 4 + 2], lp[q * 4 + 3]);
        }
        return;
    }

    // ---- Router (R3 logic, measured rel_err 0.0) + x bf16 split ----
    {
        const float4* Wp4 = reinterpret_cast<const float4*>(Wp);
        float4* swp4 = reinterpret_cast<float4*>(s_wp);
#pragma unroll
        for (int i = 0; i < 2; i++) swp4[tid + 256 * i] = Wp4[tid + 256 * i];
    }
    if (tid < EE) { s_bp[tid] = bp[tid]; s_cnt[tid] = 0; }
    __syncthreads();

    int warp = tid >> 5;
    int lane = tid & 31;
    int e_lane = lane >> 2;
    const float4* X4 = reinterpret_cast<const float4*>(x);
    float4* Y4 = reinterpret_cast<float4*>(y);

#pragma unroll 1
    for (int i = 0; i < 8; i++) {
        int row = blockIdx.x * 64 + warp * 8 + i;
        float4 xa = X4[row * 64 + lane];
        float4 xb = X4[row * 64 + 32 + lane];

        {
            uint2 ha, la, hb, lb;
            split4(xa, ha, la);
            split4(xb, hb, lb);
            *reinterpret_cast<uint2*>(g_xhi + (size_t)row * II + lane * 4) = ha;
            *reinterpret_cast<uint2*>(g_xlo + (size_t)row * II + lane * 4) = la;
            *reinterpret_cast<uint2*>(g_xhi + (size_t)row * II + 128 + lane * 4) = hb;
            *reinterpret_cast<uint2*>(g_xlo + (size_t)row * II + 128 + lane * 4) = lb;
        }

        float p[EE];
#pragma unroll
        for (int e = 0; e < EE; e++) {
            const float4* we = reinterpret_cast<const float4*>(s_wp + e * II);
            float4 wa = we[lane];
            float4 wb2 = we[32 + lane];
            p[e] = xa.x * wa.x + xa.y * wa.y + xa.z * wa.z + xa.w * wa.w
                 + xb.x * wb2.x + xb.y * wb2.y + xb.z * wb2.z + xb.w * wb2.w;
        }
#pragma unroll
        for (int s = 16; s >= 4; s >>= 1)
#pragma unroll
            for (int e = 0; e < EE; e++)
                p[e] += __shfl_xor_sync(0xffffffffu, p[e], s);
        float v = p[0];
#pragma unroll
        for (int j = 1; j < EE; j++) v = (e_lane == j) ? p[j] : v;
        v += __shfl_xor_sync(0xffffffffu, v, 1);
        v += __shfl_xor_sync(0xffffffffu, v, 2);

        float z = v + s_bp[e_lane];
        float g = 1.0f / (1.0f + expf(-z));

        float m = g;
        m = fmaxf(m, __shfl_xor_sync(0xffffffffu, m, 4));
        m = fmaxf(m, __shfl_xor_sync(0xffffffffu, m, 8));
        m = fmaxf(m, __shfl_xor_sync(0xffffffffu, m, 16));

        unsigned bal = __ballot_sync(0xffffffffu, g == m);
        int nsel = __popc(bal & 0x11111111u);

        if ((g == m) && ((lane & 3) == 0)) {
            int pos = atomicAdd(&s_cnt[e_lane], 1);
            s_list[e_lane][pos] = row | (nsel > 1 ? 0x40000000 : 0);
        }
        if (nsel > 1) {
            Y4[row * 64 + lane] = make_float4(0.f, 0.f, 0.f, 0.f);
            Y4[row * 64 + 32 + lane] = make_float4(0.f, 0.f, 0.f, 0.f);
        }
    }
    __syncthreads();

    if (tid < EE) s_base[tid] = atomicAdd(&g_counts[tid * 32], s_cnt[tid]);
    __syncthreads();

    if (warp < EE) {
        int n = s_cnt[warp];
        int b = s_base[warp];
        for (int j = lane; j < n; j += 32)
            g_rows[warp * BB + b + j] = s_list[warp][j];
    }
}

// ---------------------------------------------------------------------------
// mma.sync GEMM. grid (EE, 128): 32 gathered rows x 256 cols per block.
// 128 threads / 4 warps (warp = 64 cols). 3-term bf16 split on the tensor pipe.
// K in 4 chunks of 64, double-buffered smem fed by cp.async.
// ---------------------------------------------------------------------------
#define AP 72                       // padded row stride (elements): 144B = 36 banks
#define ABYTES (32 * AP * 2)        // 4608
#define BBYTES_T (256 * AP * 2)     // 36864
#define BUFB (2 * ABYTES + 2 * BBYTES_T)   // 82944: Ah | Al | Bh | Bl
#define SM_BUF 1024
#define SMEM_GEMM (SM_BUF + 2 * BUFB)      // 166912

__global__ __launch_bounds__(128) void gemm_kernel(float* __restrict__ y) {
    extern __shared__ char smem[];
    int tid = threadIdx.x, wid = tid >> 5, lane = tid & 31;
    int gid = lane >> 2, tig = lane & 3;
    int e = blockIdx.x, tile = blockIdx.y;
    int count = g_counts[e * 32];

    if (tile * 32 < count) {
        int nrows = min(32, count - tile * 32);
        int* rowids = reinterpret_cast<int*>(smem);
        if (tid < 32)
            rowids[tid] = (tid < nrows) ? g_rows[e * BB + tile * 32 + tid] : -1;
        __syncthreads();

        uint32_t sb = smem_to_u32(smem);

        // Loader roles
        int ar = tid >> 2;                       // A row 0..31
        int rvA = rowids[ar];
        int ridA = (rvA < 0) ? 0 : (rvA & 0x3FFFFFFF);   // dead rows read row 0, result discarded
        const __nv_bfloat16* xh = g_xhi + (size_t)ridA * II;
        const __nv_bfloat16* xl = g_xlo + (size_t)ridA * II;
        const __nv_bfloat16* wh = g_whi + (size_t)e * OO * II;
        const __nv_bfloat16* wl = g_wlo + (size_t)e * OO * II;

        auto load_chunk = [&](int c, int b) {
            uint32_t base = sb + SM_BUF + b * BUFB;
            int kc = c * 64;
            // A tile: 32 rows x 64 k, hi+lo
#pragma unroll
            for (int q = 0; q < 2; q++) {
                int cc = (tid & 3) + q * 4;          // 16B chunk 0..7
                uint32_t off = ar * 144 + cc * 16;
                cp16(base + off, xh + kc + cc * 8);
                cp16(base + ABYTES + off, xl + kc + cc * 8);
            }
            // B tile: 256 rows (o) x 64 k, hi+lo
#pragma unroll
            for (int j = 0; j < 16; j++) {
                int n = (tid >> 3) + j * 16;
                int cc = tid & 7;
                uint32_t off = n * 144 + cc * 16;
                size_t src = (size_t)n * II + kc + cc * 8;
                cp16(base + 2 * ABYTES + off, wh + src);
                cp16(base + 2 * ABYTES + BBYTES_T + off, wl + src);
            }
            asm volatile("cp.async.commit_group;" ::: "memory");
        };

        float d[2][8][4];
#pragma unroll
        for (int mt = 0; mt < 2; mt++)
#pragma unroll
            for (int nt = 0; nt < 8; nt++)
#pragma unroll
                for (int q = 0; q < 4; q++) d[mt][nt][q] = 0.f;

        load_chunk(0, 0);

#pragma unroll
        for (int c = 0; c < 4; c++) {
            if (c < 3) {
                load_chunk(c + 1, (c + 1) & 1);
                asm volatile("cp.async.wait_group 1;" ::: "memory");
            } else {
                asm volatile("cp.async.wait_group 0;" ::: "memory");
            }
            __syncthreads();

            const char* bufp = smem + SM_BUF + (c & 1) * BUFB;
            const __nv_bfloat16* Ah = reinterpret_cast<const __nv_bfloat16*>(bufp);
            const __nv_bfloat16* Al = reinterpret_cast<const __nv_bfloat16*>(bufp + ABYTES);
            const __nv_bfloat16* Bh = reinterpret_cast<const __nv_bfloat16*>(bufp + 2 * ABYTES);
            const __nv_bfloat16* Bl = reinterpret_cast<const __nv_bfloat16*>(bufp + 2 * ABYTES + BBYTES_T);

#pragma unroll
            for (int ks = 0; ks < 4; ks++) {
                int k0 = ks * 16 + 2 * tig;
                uint32_t ah[2][4], al[2][4];
#pragma unroll
                for (int mt = 0; mt < 2; mt++) {
                    const __nv_bfloat16* r0 = Ah + (mt * 16 + gid) * AP;
                    const __nv_bfloat16* r1 = r0 + 8 * AP;
                    ah[mt][0] = *reinterpret_cast<const uint32_t*>(r0 + k0);
                    ah[mt][1] = *reinterpret_cast<const uint32_t*>(r1 + k0);
                    ah[mt][2] = *reinterpret_cast<const uint32_t*>(r0 + k0 + 8);
                    ah[mt][3] = *reinterpret_cast<const uint32_t*>(r1 + k0 + 8);
                    const __nv_bfloat16* s0 = Al + (mt * 16 + gid) * AP;
                    const __nv_bfloat16* s1 = s0 + 8 * AP;
                    al[mt][0] = *reinterpret_cast<const uint32_t*>(s0 + k0);
                    al[mt][1] = *reinterpret_cast<const uint32_t*>(s1 + k0);
                    al[mt][2] = *reinterpret_cast<const uint32_t*>(s0 + k0 + 8);
                    al[mt][3] = *reinterpret_cast<const uint32_t*>(s1 + k0 + 8);
                }
#pragma unroll
                for (int nt = 0; nt < 8; nt++) {
                    int nrow = wid * 64 + nt * 8 + gid;
                    const __nv_bfloat16* bh_p = Bh + nrow * AP;
                    const __nv_bfloat16* bl_p = Bl + nrow * AP;
                    uint32_t bh[2] = {*reinterpret_cast<const uint32_t*>(bh_p + k0),
                                      *reinterpret_cast<const uint32_t*>(bh_p + k0 + 8)};
                    uint32_t bl[2] = {*reinterpret_cast<const uint32_t*>(bl_p + k0),
                                      *reinterpret_cast<const uint32_t*>(bl_p + k0 + 8)};
#pragma unroll
                    for (int mt = 0; mt < 2; mt++) {
                        MMA(d[mt][nt], ah[mt], bh);   // xh*wh
                        MMA(d[mt][nt], al[mt], bh);   // xl*wh
                        MMA(d[mt][nt], ah[mt], bl);   // xh*wl
                    }
                }
            }
            __syncthreads();
        }

        // Epilogue: scatter D fragments
#pragma unroll
        for (int mt = 0; mt < 2; mt++) {
#pragma unroll
            for (int h = 0; h < 2; h++) {
                int rr = mt * 16 + gid + h * 8;
                int rv = rowids[rr];
                if (rv < 0) continue;
                int rid = rv & 0x3FFFFFFF;
                bool multi = (rv & 0x40000000) != 0;
                float* yp = y + (size_t)rid * OO + wid * 64 + 2 * tig;
                if (multi) {
#pragma unroll
                    for (int nt = 0; nt < 8; nt++) {
                        atomicAdd(&yp[nt * 8], d[mt][nt][h * 2 + 0]);
                        atomicAdd(&yp[nt * 8 + 1], d[mt][nt][h * 2 + 1]);
                    }
                } else {
#pragma unroll
                    for (int nt = 0; nt < 8; nt++)
                        *reinterpret_cast<float2*>(&yp[nt * 8]) =
                            make_float2(d[mt][nt][h * 2 + 0], d[mt][nt][h * 2 + 1]);
                }
            }
        }
    }

    // Last block resets counters for the next graph replay.
    __syncthreads();
    if (threadIdx.x == 0) {
        int old = atomicAdd(&g_done, 1);
        if (old == EE * 128 - 1) {
#pragma unroll
            for (int i = 0; i < EE; i++) g_counts[i * 32] = 0;
            __threadfence();
            g_done = 0;
        }
    }
}

extern "C" void kernel_launch(void* const* d_in, const int* in_sizes, int n_in,
                              void* d_out, int out_size) {
    const float* x  = (const float*)d_in[0];
    const float* W  = (const float*)d_in[1];
    const float* Wp = (const float*)d_in[2];
    const float* bp = (const float*)d_in[3];
    float* y = (float*)d_out;

    cudaFuncSetAttribute(gemm_kernel, cudaFuncAttributeMaxDynamicSharedMemorySize, SMEM_GEMM);
    prep_kernel<<<128, 256>>>(x, W, Wp, bp, y);
    gemm_kernel<<<dim3(EE, 128), 128, SMEM_GEMM>>>(y);
}